// round 14
// baseline (speedup 1.0000x reference)
#include <cuda_runtime.h>
#include <cuda_bf16.h>

#define BATCH     1024
#define CODE_LEN  65536
#define HALF_F4   (CODE_LEN / 2 / 4)             /* 8192 float4 per CTA    */
#define NTHREADS  512
#define NBLOCKS   (BATCH * 2)                    /* 2048 half-row CTAs     */
#define GROUPS    (HALF_F4 / NTHREADS / 4)       /* 4 groups of 4 batches  */
#define MARGIN_F  0.01f

// Scratch (device globals; no allocation allowed)
__device__ float g_half_sse[NBLOCKS];
__device__ unsigned int g_done_count;   // zero-init; reset by last block

__device__ __forceinline__ float4 ldcs4(const float4* p) {
    float4 v;
    asm volatile("ld.global.cs.v4.f32 {%0,%1,%2,%3}, [%4];"
                 : "=f"(v.x), "=f"(v.y), "=f"(v.z), "=f"(v.w)
                 : "l"(p));
    return v;
}

__global__ __launch_bounds__(NTHREADS, 4)   // force <=32 regs -> 4 CTAs/SM
void mse_hinge_half_kernel(const float* __restrict__ z1,
                           const float* __restrict__ z2,
                           float* __restrict__ out) {
    const int half = blockIdx.x;             // 0 .. 2047
    const size_t base_el = (size_t)half * (CODE_LEN / 2);
    const float4* __restrict__ a = reinterpret_cast<const float4*>(z1 + base_el);
    const float4* __restrict__ b = reinterpret_cast<const float4*>(z2 + base_el);

    float acc0 = 0.0f, acc1 = 0.0f;
    for (int g = 0; g < GROUPS; ++g) {
        const int base = threadIdx.x + g * (NTHREADS * 4);

        // Burst-batched per stream; 4 loads 8KB-strided (proven optimum).
        float4 va[4], vb[4];
        #pragma unroll
        for (int j = 0; j < 4; ++j)
            va[j] = ldcs4(a + base + j * NTHREADS);
        #pragma unroll
        for (int j = 0; j < 4; ++j)
            vb[j] = ldcs4(b + base + j * NTHREADS);

        #pragma unroll
        for (int j = 0; j < 4; ++j) {
            float d0 = va[j].x - vb[j].x;
            float d1 = va[j].y - vb[j].y;
            float d2 = va[j].z - vb[j].z;
            float d3 = va[j].w - vb[j].w;
            acc0 = fmaf(d0, d0, acc0);
            acc1 = fmaf(d1, d1, acc1);
            acc0 = fmaf(d2, d2, acc0);
            acc1 = fmaf(d3, d3, acc1);
        }
    }
    float acc = acc0 + acc1;

    // warp reduce
    #pragma unroll
    for (int o = 16; o > 0; o >>= 1)
        acc += __shfl_xor_sync(0xffffffffu, acc, o);

    __shared__ float s_part[NTHREADS / 32];
    __shared__ bool  s_is_last;
    if ((threadIdx.x & 31) == 0)
        s_part[threadIdx.x >> 5] = acc;
    __syncthreads();

    if (threadIdx.x < 32) {
        float v = (threadIdx.x < NTHREADS / 32) ? s_part[threadIdx.x] : 0.0f;
        #pragma unroll
        for (int o = 8; o > 0; o >>= 1)
            v += __shfl_xor_sync(0xffffffffu, v, o);
        if (threadIdx.x == 0) {
            g_half_sse[half] = v;
            __threadfence();
            unsigned int prev = atomicAdd(&g_done_count, 1u);
            s_is_last = (prev == NBLOCKS - 1);
        }
    }
    __syncthreads();

    // Last-arriving block: deterministic hinge + batch mean over 1024 rows.
    if (s_is_last) {
        if (threadIdx.x == 0)
            g_done_count = 0;   // reset for next graph replay

        // 1024 rows / 512 threads = 2 rows per thread; fixed order.
        float v = 0.0f;
        #pragma unroll
        for (int r = 0; r < BATCH / NTHREADS; ++r) {
            const int rw = threadIdx.x + r * NTHREADS;
            float sse = g_half_sse[2 * rw] + g_half_sse[2 * rw + 1];
            float mse = sse * (1.0f / (float)CODE_LEN);
            v += (mse > MARGIN_F) ? (mse - MARGIN_F) : 0.0f;
        }

        #pragma unroll
        for (int o = 16; o > 0; o >>= 1)
            v += __shfl_xor_sync(0xffffffffu, v, o);

        __shared__ float s_fin[NTHREADS / 32];
        if ((threadIdx.x & 31) == 0)
            s_fin[threadIdx.x >> 5] = v;
        __syncthreads();

        if (threadIdx.x < 32) {
            float w = (threadIdx.x < NTHREADS / 32) ? s_fin[threadIdx.x] : 0.0f;
            #pragma unroll
            for (int o = 8; o > 0; o >>= 1)
                w += __shfl_xor_sync(0xffffffffu, w, o);
            if (threadIdx.x == 0)
                out[0] = w * (1.0f / (float)BATCH);
        }
    }
}

extern "C" void kernel_launch(void* const* d_in, const int* in_sizes, int n_in,
                              void* d_out, int out_size) {
    const float* z1 = (const float*)d_in[0];
    const float* z2 = (const float*)d_in[1];
    float* out = (float*)d_out;

    mse_hinge_half_kernel<<<NBLOCKS, NTHREADS>>>(z1, z2, out);
}

// round 15
// speedup vs baseline: 1.0208x; 1.0208x over previous
#include <cuda_runtime.h>
#include <cuda_bf16.h>

#define BATCH     1024
#define CODE_LEN  65536
#define NTHREADS  512
#define NF4       (CODE_LEN / 4)                 /* 16384 float4 per row */
#define GROUPS    (NF4 / NTHREADS / 4)           /* 8 groups of 4 iters  */
#define MARGIN_F  0.01f

// Scratch (device globals; no allocation allowed)
__device__ float g_row_hinged[BATCH];
__device__ unsigned int g_done_count;   // zero-init; reset by last block

__device__ __forceinline__ float4 ldcs4(const float4* p) {
    float4 v;
    asm volatile("ld.global.cs.v4.f32 {%0,%1,%2,%3}, [%4];"
                 : "=f"(v.x), "=f"(v.y), "=f"(v.z), "=f"(v.w)
                 : "l"(p));
    return v;
}

__global__ __launch_bounds__(NTHREADS, 4)   // force <=32 regs -> 4 CTAs/SM
void mse_hinge_fused_kernel(const float* __restrict__ z1,
                            const float* __restrict__ z2,
                            float* __restrict__ out) {
    const int row = blockIdx.x;
    const float4* __restrict__ a =
        reinterpret_cast<const float4*>(z1 + (size_t)row * CODE_LEN);
    const float4* __restrict__ b =
        reinterpret_cast<const float4*>(z2 + (size_t)row * CODE_LEN);

    float acc0 = 0.0f, acc1 = 0.0f;
    for (int g = 0; g < GROUPS; ++g) {
        const int base = threadIdx.x + g * (NTHREADS * 4);

        // Burst-batched: all stream-a loads first, then all stream-b loads.
        // The 4 loads per stream are 8KB-strided -> spread across LTS
        // partitions / HBM channels (stride sweep: 256B and 64KB regress,
        // 8KB is the measured optimum, 16KB ties).
        float4 va[4], vb[4];
        #pragma unroll
        for (int j = 0; j < 4; ++j)
            va[j] = ldcs4(a + base + j * NTHREADS);
        #pragma unroll
        for (int j = 0; j < 4; ++j)
            vb[j] = ldcs4(b + base + j * NTHREADS);

        #pragma unroll
        for (int j = 0; j < 4; ++j) {
            float d0 = va[j].x - vb[j].x;
            float d1 = va[j].y - vb[j].y;
            float d2 = va[j].z - vb[j].z;
            float d3 = va[j].w - vb[j].w;
            acc0 = fmaf(d0, d0, acc0);
            acc1 = fmaf(d1, d1, acc1);
            acc0 = fmaf(d2, d2, acc0);
            acc1 = fmaf(d3, d3, acc1);
        }
    }
    float acc = acc0 + acc1;

    // warp reduce
    #pragma unroll
    for (int o = 16; o > 0; o >>= 1)
        acc += __shfl_xor_sync(0xffffffffu, acc, o);

    __shared__ float s_part[NTHREADS / 32];
    __shared__ bool  s_is_last;
    if ((threadIdx.x & 31) == 0)
        s_part[threadIdx.x >> 5] = acc;
    __syncthreads();

    if (threadIdx.x < 32) {
        float v = (threadIdx.x < NTHREADS / 32) ? s_part[threadIdx.x] : 0.0f;
        #pragma unroll
        for (int o = 8; o > 0; o >>= 1)
            v += __shfl_xor_sync(0xffffffffu, v, o);
        if (threadIdx.x == 0) {
            float mse = v * (1.0f / (float)CODE_LEN);
            g_row_hinged[row] = (mse > MARGIN_F) ? (mse - MARGIN_F) : 0.0f;
            __threadfence();
            unsigned int prev = atomicAdd(&g_done_count, 1u);
            s_is_last = (prev == BATCH - 1);
        }
    }
    __syncthreads();

    // Last-arriving block performs the final deterministic reduction.
    if (s_is_last) {
        if (threadIdx.x == 0)
            g_done_count = 0;   // reset for next graph replay

        float v = g_row_hinged[threadIdx.x] + g_row_hinged[threadIdx.x + NTHREADS];

        #pragma unroll
        for (int o = 16; o > 0; o >>= 1)
            v += __shfl_xor_sync(0xffffffffu, v, o);

        __shared__ float s_fin[NTHREADS / 32];
        if ((threadIdx.x & 31) == 0)
            s_fin[threadIdx.x >> 5] = v;
        __syncthreads();

        if (threadIdx.x < 32) {
            float w = (threadIdx.x < NTHREADS / 32) ? s_fin[threadIdx.x] : 0.0f;
            #pragma unroll
            for (int o = 8; o > 0; o >>= 1)
                w += __shfl_xor_sync(0xffffffffu, w, o);
            if (threadIdx.x == 0)
                out[0] = w * (1.0f / (float)BATCH);
        }
    }
}

extern "C" void kernel_launch(void* const* d_in, const int* in_sizes, int n_in,
                              void* d_out, int out_size) {
    const float* z1 = (const float*)d_in[0];
    const float* z2 = (const float*)d_in[1];
    float* out = (float*)d_out;

    mse_hinge_fused_kernel<<<BATCH, NTHREADS>>>(z1, z2, out);
}